// round 14
// baseline (speedup 1.0000x reference)
#include <cuda_runtime.h>

#define NB 2
#define NC 256
#define NL 1536
#define NH 4
#define ND 64
#define RR 50
#define NREL 101            // 2R+1
#define TT 16               // t-tile in attention kernel
#define SW (TT + 2*RR)      // 116: s-window per t-tile

// ---------------- scratch (device globals; no allocation) ----------------
__device__ float g_q  [NB*NH*NL*ND];
__device__ float g_k  [NB*NH*NL*ND];
__device__ float g_c  [NB*NH*NL*ND];
__device__ float g_att[NB*NC*NL];
__device__ float g_y  [NB*NC*NL];
__device__ float g_sum  [NC];
__device__ float g_sumsq[NC];

// ---------------- kernel 0: zero BN accumulators ----------------
__global__ void k_zero() {
    int i = threadIdx.x;
    if (i < NC) { g_sum[i] = 0.f; g_sumsq[i] = 0.f; }
}

// ---------------- kernel 1: fused projection GEMMs (Wc, Wq, Wk in one grid) ----------------
// out[o,(b,l)] = sum_c W[o,c] * x[b,c,l] + bias[o]
// stored transposed: outT[b,h,l,d], o = h*64+d. Tile: 64(l) x 32(o).
// blockIdx.y in [0,24): wsel = y>>3 selects matrix, o0 = (y&7)*32
__global__ void __launch_bounds__(256) k_proj3(
    const float* __restrict__ Wc, const float* __restrict__ bc,
    const float* __restrict__ Wq, const float* __restrict__ bq,
    const float* __restrict__ Wk, const float* __restrict__ bk,
    const float* __restrict__ x)
{
    __shared__ float sA[16][36];   // W^T tile [k][o]
    __shared__ float sB[16][68];   // x tile   [k][l]
    __shared__ float sT[64][33];   // output staging [l][o] for coalesced store

    const int l0 = blockIdx.x * 64;
    const int wsel = blockIdx.y >> 3;
    const int o0 = (blockIdx.y & 7) * 32;
    const int b  = blockIdx.z;
    const int tid = threadIdx.x;
    const int tx = tid & 15, ty = tid >> 4;
    const int m0 = ty * 2,  j0 = tx * 4;
    const int am = tid >> 3, ak = (tid & 7) * 2;
    const int bk2 = tid >> 4, bj = (tid & 15) * 4;

    const float* W    = (wsel == 0) ? Wc : (wsel == 1) ? Wq : Wk;
    const float* bias = (wsel == 0) ? bc : (wsel == 1) ? bq : bk;
    float* outT       = (wsel == 0) ? g_c : (wsel == 1) ? g_q : g_k;
    const float* xb = x + b * NC * NL;

    float acc[2][4] = {};
    for (int c0 = 0; c0 < NC; c0 += 16) {
        float2 a2 = *(const float2*)(W + (o0 + am) * NC + c0 + ak);
        sA[ak  ][am] = a2.x;
        sA[ak+1][am] = a2.y;
        *(float4*)&sB[bk2][bj] = *(const float4*)(xb + (c0 + bk2) * NL + l0 + bj);
        __syncthreads();
        #pragma unroll
        for (int k = 0; k < 16; k++) {
            float2 av = *(const float2*)&sA[k][m0];
            float4 bv = *(const float4*)&sB[k][j0];
            acc[0][0] += av.x*bv.x; acc[0][1] += av.x*bv.y; acc[0][2] += av.x*bv.z; acc[0][3] += av.x*bv.w;
            acc[1][0] += av.y*bv.x; acc[1][1] += av.y*bv.y; acc[1][2] += av.y*bv.z; acc[1][3] += av.y*bv.w;
        }
        __syncthreads();
    }

    // stage (add bias) -> sT[l][o]
    #pragma unroll
    for (int i = 0; i < 2; i++) {
        float bv = bias[o0 + m0 + i];
        #pragma unroll
        for (int j = 0; j < 4; j++) sT[j0 + j][m0 + i] = acc[i][j] + bv;
    }
    __syncthreads();

    // coalesced store: o-tile lies within one head (o0 multiple of 32)
    const int h = o0 >> 6, dbase = o0 & 63;
    float* dst = outT + ((size_t)(b*NH + h) * NL + l0) * ND + dbase;
    #pragma unroll
    for (int it = 0; it < 8; it++) {
        int i2 = it * 256 + tid;
        int l = i2 >> 5, dd = i2 & 31;
        dst[(size_t)l * ND + dd] = sT[l][dd];
    }
}

// ---------------- kernel 2: banded attention (rel-emb dot fused in) ----------------
// grid (NL/TT, NH, NB), 256 threads, ~66.5KB dynamic smem.
__global__ void __launch_bounds__(256) k_attn(const float* __restrict__ emb)
{
    extern __shared__ float smem[];
    float (*sQ  )[65]   = (float(*)[65]  )(smem);                       // 16 x 65
    float (*sKC )[65]   = (float(*)[65]  )(smem + TT*65);               // 116 x 65
    float (*sS  )[SW+1] = (float(*)[SW+1])(smem + TT*65 + SW*65);       // 16 x 117
    float (*sEmb)[65]   = (float(*)[65]  )(smem + TT*65 + SW*65 + TT*(SW+1)); // 101 x 65

    const int t0 = blockIdx.x * TT;
    const int bh = blockIdx.z * NH + blockIdx.y;
    const int tid = threadIdx.x;
    const int s0 = t0 - RR;

    const float* qb = g_q + (size_t)(bh*NL + t0) * ND;
    for (int i = tid; i < TT*64; i += 256) sQ[i >> 6][i & 63] = qb[i];
    const float* kb = g_k + (size_t)bh * NL * ND;
    for (int i = tid; i < SW*64; i += 256) {
        int j = i >> 6, d = i & 63;
        int s = s0 + j;
        sKC[j][d] = (s >= 0 && s < NL) ? kb[(size_t)s*ND + d] : 0.f;
    }
    for (int i = tid; i < NREL*64; i += 256) sEmb[i >> 6][i & 63] = 0.3f * emb[i];
    __syncthreads();

    // scores: S[tt][j] = q[t].(k[s] + 0.3*emb[r]),  r = tt + 2R - j, band-masked
    for (int idx = tid; idx < TT*SW; idx += 256) {
        int tt = idx / SW, j = idx - tt * SW;
        int s = s0 + j;
        float v = -1e30f;
        if (s >= 0 && s < NL && j >= tt && j <= tt + 2*RR) {
            int r = tt + 2*RR - j;
            float a = 0.f;
            #pragma unroll
            for (int d = 0; d < 64; d++) a += sQ[tt][d] * (sKC[j][d] + sEmb[r][d]);
            v = a;
        }
        sS[tt][j] = v;
    }
    __syncthreads();

    // overwrite K with content (no reader of sKC between these barriers)
    const float* cb = g_c + (size_t)bh * NL * ND;
    for (int i = tid; i < SW*64; i += 256) {
        int j = i >> 6, d = i & 63;
        int s = s0 + j;
        sKC[j][d] = (s >= 0 && s < NL) ? cb[(size_t)s*ND + d] : 0.f;
    }

    // softmax: each warp owns rows (exclusive sS rows -> no race)
    {
        int w = tid >> 5, lane = tid & 31;
        for (int tt = w; tt < TT; tt += 8) {
            float m = -1e30f;
            for (int j = lane; j < SW; j += 32) m = fmaxf(m, sS[tt][j]);
            #pragma unroll
            for (int o = 16; o; o >>= 1) m = fmaxf(m, __shfl_xor_sync(0xffffffffu, m, o));
            float sum = 0.f;
            for (int j = lane; j < SW; j += 32) {
                float e = __expf(sS[tt][j] - m);
                sS[tt][j] = e;
                sum += e;
            }
            #pragma unroll
            for (int o = 16; o; o >>= 1) sum += __shfl_xor_sync(0xffffffffu, sum, o);
            float inv = 1.f / sum;
            for (int j = lane; j < SW; j += 32) sS[tt][j] *= inv;
        }
    }
    __syncthreads();

    // output: only j in [tt, tt+2R] can have w != 0, and there r = 2R - jj
    float* ob = g_att + (size_t)blockIdx.z * NC * NL + (size_t)blockIdx.y * 64 * NL;
    for (int idx = tid; idx < TT*64; idx += 256) {
        int tt = idx >> 6, c = idx & 63;
        float acc = 0.f;
        #pragma unroll 4
        for (int jj = 0; jj < NREL; jj++) {
            int j = tt + jj;
            float w = sS[tt][j];
            acc += w * (sKC[j][c] + sEmb[2*RR - jj][c]);
        }
        ob[(size_t)c * NL + t0 + tt] = acc;
    }
}

// ---------------- kernel 3: final projection Wf + bias, fused BN stats ----------------
// Tile: 64(l) x 32(o). grid (NL/64, NC/32, NB) = 384 CTAs.
__global__ void __launch_bounds__(256) k_final(
    const float* __restrict__ W, const float* __restrict__ bias)
{
    __shared__ float sA[16][36];
    __shared__ float sB[16][68];

    const int l0 = blockIdx.x * 64;
    const int o0 = blockIdx.y * 32;
    const int b  = blockIdx.z;
    const int tid = threadIdx.x;
    const int tx = tid & 15, ty = tid >> 4;
    const int m0 = ty * 2,  j0 = tx * 4;
    const int am = tid >> 3, ak = (tid & 7) * 2;
    const int bk2 = tid >> 4, bj = (tid & 15) * 4;
    const float* xb = g_att + (size_t)b * NC * NL;

    float acc[2][4] = {};
    for (int c0 = 0; c0 < NC; c0 += 16) {
        float2 a2 = *(const float2*)(W + (o0 + am) * NC + c0 + ak);
        sA[ak  ][am] = a2.x;
        sA[ak+1][am] = a2.y;
        *(float4*)&sB[bk2][bj] = *(const float4*)(xb + (c0 + bk2) * NL + l0 + bj);
        __syncthreads();
        #pragma unroll
        for (int k = 0; k < 16; k++) {
            float2 av = *(const float2*)&sA[k][m0];
            float4 bv = *(const float4*)&sB[k][j0];
            acc[0][0] += av.x*bv.x; acc[0][1] += av.x*bv.y; acc[0][2] += av.x*bv.z; acc[0][3] += av.x*bv.w;
            acc[1][0] += av.y*bv.x; acc[1][1] += av.y*bv.y; acc[1][2] += av.y*bv.z; acc[1][3] += av.y*bv.w;
        }
        __syncthreads();
    }

    float* yb = g_y + (size_t)b * NC * NL;
    #pragma unroll
    for (int i = 0; i < 2; i++) {
        int o = o0 + m0 + i;
        float bv = bias[o];
        float4 v4;
        v4.x = acc[i][0] + bv; v4.y = acc[i][1] + bv;
        v4.z = acc[i][2] + bv; v4.w = acc[i][3] + bv;
        *(float4*)&yb[(size_t)o * NL + l0 + j0] = v4;
        float s1 = v4.x + v4.y + v4.z + v4.w;
        float s2 = v4.x*v4.x + v4.y*v4.y + v4.z*v4.z + v4.w*v4.w;
        // reduce across the 16 tx lanes (xor <= 8 stays within each 16-lane half)
        #pragma unroll
        for (int off = 8; off; off >>= 1) {
            s1 += __shfl_xor_sync(0xffffffffu, s1, off);
            s2 += __shfl_xor_sync(0xffffffffu, s2, off);
        }
        if (tx == 0) {
            atomicAdd(&g_sum[o],   s1);
            atomicAdd(&g_sumsq[o], s2);
        }
    }
}

// ---------------- kernel 4: BN finalize + ReLU + scale (float4) ----------------
__global__ void __launch_bounds__(256) k_bn(
    const float* __restrict__ gamma, const float* __restrict__ beta,
    const float* __restrict__ scale, float* __restrict__ out)
{
    int idx4 = blockIdx.x * 256 + threadIdx.x;
    if (idx4 >= NB*NC*NL/4) return;
    int ch = (idx4 / (NL/4)) & (NC - 1);
    const float invN = 1.f / (float)(NB * NL);
    float mean = g_sum[ch] * invN;
    float var  = g_sumsq[ch] * invN - mean * mean;
    float a = rsqrtf(var + 1e-5f) * gamma[ch];
    float bta = beta[ch], sc = scale[ch];
    float4 v = *(const float4*)&g_y[idx4 * 4];
    float4 r;
    r.x = fmaxf((v.x - mean) * a + bta, 0.f) * sc;
    r.y = fmaxf((v.y - mean) * a + bta, 0.f) * sc;
    r.z = fmaxf((v.z - mean) * a + bta, 0.f) * sc;
    r.w = fmaxf((v.w - mean) * a + bta, 0.f) * sc;
    *(float4*)&out[idx4 * 4] = r;
}

// ---------------- launch ----------------
extern "C" void kernel_launch(void* const* d_in, const int* in_sizes, int n_in,
                              void* d_out, int out_size)
{
    const float* x     = (const float*)d_in[0];
    const float* Wc    = (const float*)d_in[1];
    const float* bc    = (const float*)d_in[2];
    const float* Wq    = (const float*)d_in[3];
    const float* bq    = (const float*)d_in[4];
    const float* Wk    = (const float*)d_in[5];
    const float* bk    = (const float*)d_in[6];
    const float* emb   = (const float*)d_in[7];
    const float* Wf    = (const float*)d_in[8];
    const float* bf    = (const float*)d_in[9];
    const float* gamma = (const float*)d_in[10];
    const float* beta  = (const float*)d_in[11];
    const float* scale = (const float*)d_in[12];
    float* out = (float*)d_out;

    const int SMEM_ATTN = (TT*65 + SW*65 + TT*(SW+1) + NREL*65) * (int)sizeof(float);
    cudaFuncSetAttribute(k_attn, cudaFuncAttributeMaxDynamicSharedMemorySize, SMEM_ATTN);

    k_zero<<<1, 256>>>();

    dim3 gP(NL/64, 24, NB);
    k_proj3<<<gP, 256>>>(Wc, bc, Wq, bq, Wk, bk, x);

    dim3 gA(NL/TT, NH, NB);
    k_attn<<<gA, 256, SMEM_ATTN>>>(emb);

    dim3 gF(NL/64, NC/32, NB);
    k_final<<<gF, 256>>>(Wf, bf);

    int total4 = NB*NC*NL/4;
    k_bn<<<(total4 + 255)/256, 256>>>(gamma, beta, scale, out);
}

// round 15
// speedup vs baseline: 1.3960x; 1.3960x over previous
#include <cuda_runtime.h>

#define NB 2
#define NC 256
#define NL 1536
#define NH 4
#define ND 64
#define RR 50
#define NREL 101            // 2R+1
#define TT 16               // t-tile in attention kernel
#define SW (TT + 2*RR)      // 116: s-window per t-tile

// ---------------- scratch (device globals; no allocation) ----------------
__device__ float g_q  [NB*NH*NL*ND];
__device__ float g_k  [NB*NH*NL*ND];
__device__ float g_c  [NB*NH*NL*ND];
__device__ float g_att[NB*NC*NL];
__device__ float g_y  [NB*NC*NL];
__device__ float g_sum  [NC];
__device__ float g_sumsq[NC];

// ---------------- kernel 0: zero BN accumulators ----------------
__global__ void k_zero() {
    int i = threadIdx.x;
    if (i < NC) { g_sum[i] = 0.f; g_sumsq[i] = 0.f; }
}

// ---------------- kernel 1: fused projection GEMMs, double-buffered ----------------
// out[o,(b,l)] = sum_c W[o,c] * x[b,c,l] + bias[o]
// stored transposed: outT[b,h,l,d], o = h*64+d. Tile 64(l) x 64(o), 4x4 acc.
// blockIdx.y in [0,12): wsel = y>>2, o0 = (y&3)*64 (one full head per tile)
__global__ void __launch_bounds__(256) k_proj3(
    const float* __restrict__ Wc, const float* __restrict__ bc,
    const float* __restrict__ Wq, const float* __restrict__ bq,
    const float* __restrict__ Wk, const float* __restrict__ bk,
    const float* __restrict__ x)
{
    __shared__ float sA[2][16][68];
    __shared__ float sB[2][16][68];
    __shared__ float sT[64][68];      // output staging [l][d]

    const int l0 = blockIdx.x * 64;
    const int wsel = blockIdx.y >> 2;
    const int o0 = (blockIdx.y & 3) * 64;
    const int b  = blockIdx.z;
    const int tid = threadIdx.x;
    const int tx = tid & 15, ty = tid >> 4;
    const int m0 = ty * 4,  j0 = tx * 4;
    const int am = tid >> 2, ak = (tid & 3) * 4;
    const int bk2 = tid >> 4, bj = (tid & 15) * 4;

    const float* W    = (wsel == 0) ? Wc : (wsel == 1) ? Wq : Wk;
    const float* bias = (wsel == 0) ? bc : (wsel == 1) ? bq : bk;
    float* outT       = (wsel == 0) ? g_c : (wsel == 1) ? g_q : g_k;
    const float* xb = x + b * NC * NL;

    const float* aPtr = W + (o0 + am) * NC + ak;       // + s*16
    const float* bPtr = xb + (size_t)bk2 * NL + l0 + bj; // + s*16*NL

    float acc[4][4] = {};
    float4 a4 = *(const float4*)(aPtr);
    float4 b4 = *(const float4*)(bPtr);
    sA[0][ak+0][am] = a4.x; sA[0][ak+1][am] = a4.y;
    sA[0][ak+2][am] = a4.z; sA[0][ak+3][am] = a4.w;
    *(float4*)&sB[0][bk2][bj] = b4;
    __syncthreads();

    #pragma unroll
    for (int s = 0; s < 16; s++) {
        const int cur = s & 1;
        if (s < 15) {
            a4 = *(const float4*)(aPtr + (s+1)*16);
            b4 = *(const float4*)(bPtr + (size_t)(s+1)*16*NL);
        }
        #pragma unroll
        for (int k = 0; k < 16; k++) {
            float4 av = *(const float4*)&sA[cur][k][m0];
            float4 bv = *(const float4*)&sB[cur][k][j0];
            acc[0][0] += av.x*bv.x; acc[0][1] += av.x*bv.y; acc[0][2] += av.x*bv.z; acc[0][3] += av.x*bv.w;
            acc[1][0] += av.y*bv.x; acc[1][1] += av.y*bv.y; acc[1][2] += av.y*bv.z; acc[1][3] += av.y*bv.w;
            acc[2][0] += av.z*bv.x; acc[2][1] += av.z*bv.y; acc[2][2] += av.z*bv.z; acc[2][3] += av.z*bv.w;
            acc[3][0] += av.w*bv.x; acc[3][1] += av.w*bv.y; acc[3][2] += av.w*bv.z; acc[3][3] += av.w*bv.w;
        }
        if (s < 15) {
            sA[!cur][ak+0][am] = a4.x; sA[!cur][ak+1][am] = a4.y;
            sA[!cur][ak+2][am] = a4.z; sA[!cur][ak+3][am] = a4.w;
            *(float4*)&sB[!cur][bk2][bj] = b4;
            __syncthreads();
        }
    }
    __syncthreads();

    // stage (add bias) -> sT[l][d]
    #pragma unroll
    for (int i = 0; i < 4; i++) {
        float bv = bias[o0 + m0 + i];
        #pragma unroll
        for (int j = 0; j < 4; j++) sT[j0 + j][m0 + i] = acc[i][j] + bv;
    }
    __syncthreads();

    // coalesced float4 store: o-tile is exactly one head
    const int h = o0 >> 6;
    float* dst = outT + ((size_t)(b*NH + h) * NL + l0) * ND;
    #pragma unroll
    for (int it = 0; it < 4; it++) {
        int idx4 = it * 256 + tid;              // 64*16 float4s
        int l = idx4 >> 4, dq = (idx4 & 15) * 4;
        *(float4*)&dst[(size_t)l * ND + dq] = *(const float4*)&sT[l][dq];
    }
}

// ---------------- kernel 2: banded attention, register-tiled passes ----------------
// grid (NL/TT, NH, NB), 256 threads, ~82.8KB dynamic smem.
__global__ void __launch_bounds__(256) k_attn(const float* __restrict__ emb)
{
    extern __shared__ float smem[];
    float (*sQ  )[68]   = (float(*)[68] )(smem);                         // 16 x 68
    float (*sKC )[68]   = (float(*)[68] )(smem + TT*68);                 // 116 x 68
    float (*sEmb)[68]   = (float(*)[68] )(smem + (TT+SW)*68);            // 101 x 68
    float (*sS  )[120]  = (float(*)[120])(smem + (TT+SW+NREL)*68);       // 16 x 120
    float (*sG  )[104]  = (float(*)[104])(smem + (TT+SW+NREL)*68 + TT*120); // 16 x 104
    float (*sOut)[20]   = (float(*)[20] )(smem + (TT+SW+NREL)*68 + TT*120 + TT*104); // 64 x 20

    const int t0 = blockIdx.x * TT;
    const int bh = blockIdx.z * NH + blockIdx.y;
    const int tid = threadIdx.x;
    const int s0 = t0 - RR;

    // ---- stage Q, K, 0.3*emb (float4) ----
    const float* qb = g_q + (size_t)(bh*NL + t0) * ND;
    {
        int i = tid;                       // 16*16 = 256 float4s exactly
        int r = i >> 4, dq = (i & 15) * 4;
        *(float4*)&sQ[r][dq] = *(const float4*)&qb[r*64 + dq];
    }
    const float* kb = g_k + (size_t)bh * NL * ND;
    for (int i = tid; i < SW*16; i += 256) {
        int j = i >> 4, dq = (i & 15) * 4;
        int s = s0 + j;
        float4 v = make_float4(0.f,0.f,0.f,0.f);
        if (s >= 0 && s < NL) v = *(const float4*)&kb[(size_t)s*64 + dq];
        *(float4*)&sKC[j][dq] = v;
    }
    for (int i = tid; i < NREL*16; i += 256) {
        int r = i >> 4, dq = (i & 15) * 4;
        float4 v = *(const float4*)&emb[r*64 + dq];
        v.x *= 0.3f; v.y *= 0.3f; v.z *= 0.3f; v.w *= 0.3f;
        *(float4*)&sEmb[r][dq] = v;
    }
    __syncthreads();

    // ---- G-pass: G[tt][r] = q[tt] . (0.3*emb[r]) ; tiles 2tt x 4r ----
    {
        int tg = tid >> 5, lane = tid & 31;
        if (lane < 26) {
            int tt0 = tg * 2;
            float acc0[4] = {}, acc1[4] = {};
            for (int d = 0; d < 64; d += 4) {
                float4 q0 = *(const float4*)&sQ[tt0  ][d];
                float4 q1 = *(const float4*)&sQ[tt0+1][d];
                #pragma unroll
                for (int i = 0; i < 4; i++) {
                    int r = lane + 26*i;
                    if (r < NREL) {
                        float4 e = *(const float4*)&sEmb[r][d];
                        acc0[i] += q0.x*e.x + q0.y*e.y + q0.z*e.z + q0.w*e.w;
                        acc1[i] += q1.x*e.x + q1.y*e.y + q1.z*e.z + q1.w*e.w;
                    }
                }
            }
            #pragma unroll
            for (int i = 0; i < 4; i++) {
                int r = lane + 26*i;
                if (r < NREL) { sG[tt0][r] = acc0[i]; sG[tt0+1][r] = acc1[i]; }
            }
        }
    }
    __syncthreads();

    // ---- S-pass: S[tt][j] = q.k + G[tt][tt+2R-j], band mask; tiles 2tt x 4j ----
    {
        int tg = tid >> 5, lane = tid & 31;
        if (lane < 29) {
            int tt0 = tg * 2;
            float acc0[4] = {}, acc1[4] = {};
            for (int d = 0; d < 64; d += 4) {
                float4 q0 = *(const float4*)&sQ[tt0  ][d];
                float4 q1 = *(const float4*)&sQ[tt0+1][d];
                #pragma unroll
                for (int i = 0; i < 4; i++) {
                    int j = lane + 29*i;
                    float4 k4 = *(const float4*)&sKC[j][d];
                    acc0[i] += q0.x*k4.x + q0.y*k4.y + q0.z*k4.z + q0.w*k4.w;
                    acc1[i] += q1.x*k4.x + q1.y*k4.y + q1.z*k4.z + q1.w*k4.w;
                }
            }
            #pragma unroll
            for (int i = 0; i < 4; i++) {
                int j = lane + 29*i;
                int s = s0 + j;
                #pragma unroll
                for (int ii = 0; ii < 2; ii++) {
                    int tt = tt0 + ii;
                    float v = -1e30f;
                    if (s >= 0 && s < NL && j >= tt && j <= tt + 2*RR)
                        v = (ii ? acc1[i] : acc0[i]) + sG[tt][tt + 2*RR - j];
                    sS[tt][j] = v;
                }
            }
        }
    }
    __syncthreads();

    // ---- overwrite K with content (readers of K are done) ----
    const float* cb = g_c + (size_t)bh * NL * ND;
    for (int i = tid; i < SW*16; i += 256) {
        int j = i >> 4, dq = (i & 15) * 4;
        int s = s0 + j;
        float4 v = make_float4(0.f,0.f,0.f,0.f);
        if (s >= 0 && s < NL) v = *(const float4*)&cb[(size_t)s*64 + dq];
        *(float4*)&sKC[j][dq] = v;
    }

    // ---- softmax: each warp owns exclusive rows ----
    {
        int w = tid >> 5, lane = tid & 31;
        for (int tt = w; tt < TT; tt += 8) {
            float m = -1e30f;
            for (int j = lane; j < SW; j += 32) m = fmaxf(m, sS[tt][j]);
            #pragma unroll
            for (int o = 16; o; o >>= 1) m = fmaxf(m, __shfl_xor_sync(0xffffffffu, m, o));
            float sum = 0.f;
            for (int j = lane; j < SW; j += 32) {
                float e = __expf(sS[tt][j] - m);
                sS[tt][j] = e;
                sum += e;
            }
            #pragma unroll
            for (int o = 16; o; o >>= 1) sum += __shfl_xor_sync(0xffffffffu, sum, o);
            float inv = 1.f / sum;
            for (int j = lane; j < SW; j += 32) sS[tt][j] *= inv;
        }
    }
    __syncthreads();

    // ---- O-pass: out[tt][c] = sum_jj w[tt][tt+jj]*(content[tt+jj][c] + 0.3emb[2R-jj][c]) ----
    {
        int tt = tid >> 4, c = (tid & 15) * 4;
        float ax = 0.f, ay = 0.f, az = 0.f, aw = 0.f;
        #pragma unroll 4
        for (int jj = 0; jj < NREL; jj++) {
            float w = sS[tt][tt + jj];
            float4 cv = *(const float4*)&sKC[tt + jj][c];
            float4 ev = *(const float4*)&sEmb[2*RR - jj][c];
            ax += w * (cv.x + ev.x);
            ay += w * (cv.y + ev.y);
            az += w * (cv.z + ev.z);
            aw += w * (cv.w + ev.w);
        }
        sOut[c+0][tt] = ax; sOut[c+1][tt] = ay;
        sOut[c+2][tt] = az; sOut[c+3][tt] = aw;
    }
    __syncthreads();

    // ---- coalesced store: ob[c][t0..t0+15], one float4 per thread ----
    {
        float* ob = g_att + (size_t)blockIdx.z * NC * NL + (size_t)blockIdx.y * 64 * NL;
        int c = tid >> 2, i4 = (tid & 3) * 4;
        *(float4*)&ob[(size_t)c * NL + t0 + i4] = *(const float4*)&sOut[c][i4];
    }
}

// ---------------- kernel 3: final projection Wf + bias, double-buffered, fused BN stats ----------------
// Tile 64(l) x 64(o), grid (NL/64, NC/64, NB) = 192.
__global__ void __launch_bounds__(256) k_final(
    const float* __restrict__ W, const float* __restrict__ bias)
{
    __shared__ float sA[2][16][68];
    __shared__ float sB[2][16][68];

    const int l0 = blockIdx.x * 64;
    const int o0 = blockIdx.y * 64;
    const int b  = blockIdx.z;
    const int tid = threadIdx.x;
    const int tx = tid & 15, ty = tid >> 4;
    const int m0 = ty * 4,  j0 = tx * 4;
    const int am = tid >> 2, ak = (tid & 3) * 4;
    const int bk2 = tid >> 4, bj = (tid & 15) * 4;
    const float* xb = g_att + (size_t)b * NC * NL;

    const float* aPtr = W + (o0 + am) * NC + ak;
    const float* bPtr = xb + (size_t)bk2 * NL + l0 + bj;

    float acc[4][4] = {};
    float4 a4 = *(const float4*)(aPtr);
    float4 b4 = *(const float4*)(bPtr);
    sA[0][ak+0][am] = a4.x; sA[0][ak+1][am] = a4.y;
    sA[0][ak+2][am] = a4.z; sA[0][ak+3][am] = a4.w;
    *(float4*)&sB[0][bk2][bj] = b4;
    __syncthreads();

    #pragma unroll
    for (int s = 0; s < 16; s++) {
        const int cur = s & 1;
        if (s < 15) {
            a4 = *(const float4*)(aPtr + (s+1)*16);
            b4 = *(const float4*)(bPtr + (size_t)(s+1)*16*NL);
        }
        #pragma unroll
        for (int k = 0; k < 16; k++) {
            float4 av = *(const float4*)&sA[cur][k][m0];
            float4 bv = *(const float4*)&sB[cur][k][j0];
            acc[0][0] += av.x*bv.x; acc[0][1] += av.x*bv.y; acc[0][2] += av.x*bv.z; acc[0][3] += av.x*bv.w;
            acc[1][0] += av.y*bv.x; acc[1][1] += av.y*bv.y; acc[1][2] += av.y*bv.z; acc[1][3] += av.y*bv.w;
            acc[2][0] += av.z*bv.x; acc[2][1] += av.z*bv.y; acc[2][2] += av.z*bv.z; acc[2][3] += av.z*bv.w;
            acc[3][0] += av.w*bv.x; acc[3][1] += av.w*bv.y; acc[3][2] += av.w*bv.z; acc[3][3] += av.w*bv.w;
        }
        if (s < 15) {
            sA[!cur][ak+0][am] = a4.x; sA[!cur][ak+1][am] = a4.y;
            sA[!cur][ak+2][am] = a4.z; sA[!cur][ak+3][am] = a4.w;
            *(float4*)&sB[!cur][bk2][bj] = b4;
            __syncthreads();
        }
    }

    float* yb = g_y + (size_t)b * NC * NL;
    #pragma unroll
    for (int i = 0; i < 4; i++) {
        int o = o0 + m0 + i;
        float bv = bias[o];
        float4 v4;
        v4.x = acc[i][0] + bv; v4.y = acc[i][1] + bv;
        v4.z = acc[i][2] + bv; v4.w = acc[i][3] + bv;
        *(float4*)&yb[(size_t)o * NL + l0 + j0] = v4;
        float s1 = v4.x + v4.y + v4.z + v4.w;
        float s2 = v4.x*v4.x + v4.y*v4.y + v4.z*v4.z + v4.w*v4.w;
        #pragma unroll
        for (int off = 8; off; off >>= 1) {
            s1 += __shfl_xor_sync(0xffffffffu, s1, off);
            s2 += __shfl_xor_sync(0xffffffffu, s2, off);
        }
        if (tx == 0) {
            atomicAdd(&g_sum[o],   s1);
            atomicAdd(&g_sumsq[o], s2);
        }
    }
}

// ---------------- kernel 4: BN finalize + ReLU + scale (float4) ----------------
__global__ void __launch_bounds__(256) k_bn(
    const float* __restrict__ gamma, const float* __restrict__ beta,
    const float* __restrict__ scale, float* __restrict__ out)
{
    int idx4 = blockIdx.x * 256 + threadIdx.x;
    if (idx4 >= NB*NC*NL/4) return;
    int ch = (idx4 / (NL/4)) & (NC - 1);
    const float invN = 1.f / (float)(NB * NL);
    float mean = g_sum[ch] * invN;
    float var  = g_sumsq[ch] * invN - mean * mean;
    float a = rsqrtf(var + 1e-5f) * gamma[ch];
    float bta = beta[ch], sc = scale[ch];
    float4 v = *(const float4*)&g_y[idx4 * 4];
    float4 r;
    r.x = fmaxf((v.x - mean) * a + bta, 0.f) * sc;
    r.y = fmaxf((v.y - mean) * a + bta, 0.f) * sc;
    r.z = fmaxf((v.z - mean) * a + bta, 0.f) * sc;
    r.w = fmaxf((v.w - mean) * a + bta, 0.f) * sc;
    *(float4*)&out[idx4 * 4] = r;
}

// ---------------- launch ----------------
extern "C" void kernel_launch(void* const* d_in, const int* in_sizes, int n_in,
                              void* d_out, int out_size)
{
    const float* x     = (const float*)d_in[0];
    const float* Wc    = (const float*)d_in[1];
    const float* bc    = (const float*)d_in[2];
    const float* Wq    = (const float*)d_in[3];
    const float* bq    = (const float*)d_in[4];
    const float* Wk    = (const float*)d_in[5];
    const float* bk    = (const float*)d_in[6];
    const float* emb   = (const float*)d_in[7];
    const float* Wf    = (const float*)d_in[8];
    const float* bf    = (const float*)d_in[9];
    const float* gamma = (const float*)d_in[10];
    const float* beta  = (const float*)d_in[11];
    const float* scale = (const float*)d_in[12];
    float* out = (float*)d_out;

    const int SMEM_ATTN = ((TT + SW + NREL)*68 + TT*120 + TT*104 + 64*20) * (int)sizeof(float);
    cudaFuncSetAttribute(k_attn, cudaFuncAttributeMaxDynamicSharedMemorySize, SMEM_ATTN);

    k_zero<<<1, 256>>>();

    dim3 gP(NL/64, 12, NB);
    k_proj3<<<gP, 256>>>(Wc, bc, Wq, bq, Wk, bk, x);

    dim3 gA(NL/TT, NH, NB);
    k_attn<<<gA, 256, SMEM_ATTN>>>(emb);

    dim3 gF(NL/64, NC/64, NB);
    k_final<<<gF, 256>>>(Wf, bf);

    int total4 = NB*NC*NL/4;
    k_bn<<<(total4 + 255)/256, 256>>>(gamma, beta, scale, out);
}